// round 5
// baseline (speedup 1.0000x reference)
#include <cuda_runtime.h>
#include <cuda_fp16.h>
#include <cstdint>

#define NBLOCKS 6250
#define SROW 72                       // padded floats per A row (conflict-free LDS)
#define ABUF (128 * SROW)             // floats per A buffer
#define SMEM_FLOATS (2 * ABUF + 128)
#define SMEM_BYTES (SMEM_FLOATS * 4)

// fp16 B fragments for mma.m16n8k16, laid out so each thread's per-k16-step
// fetch is 4 coalesced LDG.128:
// g_Bf16[(((wn*16 + ks)*32 + lane)*16) + nt*2 + j]
//   = half2(W[wn*64+nt*8+g][ks*16+2t+8j], W[...][ks*16+2t+8j+1])
__device__ uint32_t g_Bf16[16384];    // 64 KB, L1/L2-resident

__global__ void prep_b16(const float* __restrict__ W) {
    int i = blockIdx.x * 256 + threadIdx.x;   // 0..16383
    int wn   = i >> 13;
    int rem  = i & 8191;
    int ks   = rem >> 9;
    int rem2 = rem & 511;
    int lane = rem2 >> 4;
    int idx  = rem2 & 15;
    int nt = idx >> 1, j = idx & 1;
    int g = lane >> 2, t = lane & 3;
    int n = wn * 64 + nt * 8 + g;
    int k = ks * 16 + 2 * t + 8 * j;
    __half2 h = __floats2half2_rn(W[n * 256 + k], W[n * 256 + k + 1]);
    g_Bf16[i] = *(uint32_t*)&h;
}

__device__ __forceinline__ uint32_t smem_u32(const void* p) {
    uint32_t a;
    asm("{ .reg .u64 t; cvta.to.shared.u64 t, %1; cvt.u32.u64 %0, t; }" : "=r"(a) : "l"(p));
    return a;
}
__device__ __forceinline__ void cp16(uint32_t dst, const float* src) {
    asm volatile("cp.async.cg.shared.global [%0], [%1], 16;" :: "r"(dst), "l"(src));
}
__device__ __forceinline__ uint32_t pack_h2(float2 v) {
    __half2 h = __floats2half2_rn(v.x, v.y);
    return *(uint32_t*)&h;
}
__device__ __forceinline__ void mma16(float* acc, uint32_t a0, uint32_t a1,
                                      uint32_t a2, uint32_t a3,
                                      uint32_t b0, uint32_t b1) {
    asm volatile(
        "mma.sync.aligned.m16n8k16.row.col.f32.f16.f16.f32 "
        "{%0,%1,%2,%3}, {%4,%5,%6,%7}, {%8,%9}, {%0,%1,%2,%3};\n"
        : "+f"(acc[0]), "+f"(acc[1]), "+f"(acc[2]), "+f"(acc[3])
        : "r"(a0), "r"(a1), "r"(a2), "r"(a3), "r"(b0), "r"(b1));
}

// CTA: 128 edges x 128 outputs. 256 threads = 8 warps (4M x 2N), warp tile 32x64.
// K=256 in four 64-chunks; A (fp32) double-buffered via cp.async; B fp16
// fragments via LDG; A fragments converted fp32->fp16 at use.
__global__ void __launch_bounds__(256, 2) msg_mma_kernel(
    const float* __restrict__ H,
    const float* __restrict__ E,
    const int*   __restrict__ heads,
    const float* __restrict__ bias,
    float*       __restrict__ out)
{
    extern __shared__ __align__(16) float smem_f[];
    float* bias_s = smem_f + 2 * ABUF;
    const uint32_t s_abase = smem_u32(smem_f);

    const int tid  = threadIdx.x;
    const int warp = tid >> 5;
    const int lane = tid & 31;
    const int warp_m = warp >> 1;       // 0..3 -> rows warp_m*32
    const int warp_n = warp & 1;        // 0..1 -> cols warp_n*64
    const int g = lane >> 2;            // 0..7
    const int t = lane & 3;             // 0..3
    const int block_m = blockIdx.x * 128;

    if (tid < 128) bias_s[tid] = bias[tid];

    // Each thread loads HALF an A row per chunk: row = tid>>1, cols (tid&1)*32..+32
    const int a_row  = tid >> 1;
    const int a_coff = (tid & 1) * 32;
    const int a_head = heads[block_m + a_row];
    const float* srcH = H + (size_t)a_head * 128 + a_coff;
    const float* srcE = E + (size_t)(block_m + a_row) * 128 + a_coff;
    const uint32_t a_dst_base = s_abase + (uint32_t)((a_row * SROW + a_coff) * 4);

    float acc[2][8][4];
    #pragma unroll
    for (int mt = 0; mt < 2; mt++)
        #pragma unroll
        for (int nt = 0; nt < 8; nt++)
            #pragma unroll
            for (int i = 0; i < 4; i++) acc[mt][nt][i] = 0.0f;

    // ---- prefetch K-chunk c (64 floats per row; this thread: 32) into buf c&1 ----
    auto prefetch = [&](int c) {
        const float* src = (c < 2) ? (srcH + c * 64) : (srcE + (c - 2) * 64);
        uint32_t dst = a_dst_base + (uint32_t)((c & 1) * ABUF * 4);
        #pragma unroll
        for (int i = 0; i < 8; i++) cp16(dst + i * 16, src + i * 4);
        asm volatile("cp.async.commit_group;" ::: "memory");
    };

    prefetch(0);
    prefetch(1);

    #pragma unroll 1
    for (int c = 0; c < 4; c++) {
        if (c == 3) asm volatile("cp.async.wait_group 0;" ::: "memory");
        else        asm volatile("cp.async.wait_group 1;" ::: "memory");
        __syncthreads();

        const float* Abuf = smem_f + (c & 1) * ABUF;
        #pragma unroll
        for (int ksl = 0; ksl < 4; ksl++) {       // 4 x k16 per 64-chunk
            const int ks = c * 4 + ksl;           // global k16 step
            const int kl2 = ksl * 16 + 2 * t;     // fragment k base within chunk
            // ---- B fragments: 4 x LDG.128, coalesced, L1-hot ----
            const uint4* bp = (const uint4*)g_Bf16 + ((warp_n * 16 + ks) * 32 + lane) * 4;
            uint4 q0 = bp[0], q1 = bp[1], q2 = bp[2], q3 = bp[3];
            uint32_t bf[8][2] = {
                {q0.x, q0.y}, {q0.z, q0.w},
                {q1.x, q1.y}, {q1.z, q1.w},
                {q2.x, q2.y}, {q2.z, q2.w},
                {q3.x, q3.y}, {q3.z, q3.w}};
            #pragma unroll
            for (int mt = 0; mt < 2; mt++) {
                const int row0 = warp_m * 32 + mt * 16 + g;
                float2 p0 = *(const float2*)(Abuf + row0 * SROW + kl2);
                float2 p1 = *(const float2*)(Abuf + (row0 + 8) * SROW + kl2);
                float2 p2 = *(const float2*)(Abuf + row0 * SROW + kl2 + 8);
                float2 p3 = *(const float2*)(Abuf + (row0 + 8) * SROW + kl2 + 8);
                uint32_t a0 = pack_h2(p0);
                uint32_t a1 = pack_h2(p1);
                uint32_t a2 = pack_h2(p2);
                uint32_t a3 = pack_h2(p3);
                #pragma unroll
                for (int nt = 0; nt < 8; nt++)
                    mma16(acc[mt][nt], a0, a1, a2, a3, bf[nt][0], bf[nt][1]);
            }
        }
        if (c < 2) {
            __syncthreads();
            prefetch(c + 2);
        }
    }

    // ---- Epilogue: +bias, fp32 stores ----
    #pragma unroll
    for (int mt = 0; mt < 2; mt++) {
        const int row0 = block_m + warp_m * 32 + mt * 16 + g;
        #pragma unroll
        for (int nt = 0; nt < 8; nt++) {
            const int col = warp_n * 64 + nt * 8 + t * 2;
            float2 bv = *(const float2*)(bias_s + col);
            float2 v0, v1;
            v0.x = acc[mt][nt][0] + bv.x;
            v0.y = acc[mt][nt][1] + bv.y;
            v1.x = acc[mt][nt][2] + bv.x;
            v1.y = acc[mt][nt][3] + bv.y;
            *(float2*)(out + (size_t)row0 * 128 + col)       = v0;
            *(float2*)(out + (size_t)(row0 + 8) * 128 + col) = v1;
        }
    }
}

extern "C" void kernel_launch(void* const* d_in, const int* in_sizes, int n_in,
                              void* d_out, int out_size) {
    const float* H     = (const float*)d_in[0];
    const float* E     = (const float*)d_in[1];
    const int*   heads = (const int*)d_in[2];
    // d_in[3] = queries (unused)
    const float* W     = (const float*)d_in[4];
    const float* b     = (const float*)d_in[5];
    float* out = (float*)d_out;

    cudaFuncSetAttribute(msg_mma_kernel,
                         cudaFuncAttributeMaxDynamicSharedMemorySize, SMEM_BYTES);

    prep_b16<<<64, 256>>>(W);
    msg_mma_kernel<<<NBLOCKS, 256, SMEM_BYTES>>>(H, E, heads, b, out);
}